// round 15
// baseline (speedup 1.0000x reference)
#include <cuda_runtime.h>
#include <cuda_bf16.h>
#include <math.h>
#include <stdint.h>

// TContrastive: bf16 mma.sync 128x128 tiles @ 2 CTAs/SM, cp.async 4-stage
// pipeline (wait_group 2, literal stage offsets), dynamic smem 64KB.

#define NS 8192
#define DD 1024
#define STAGE_B 16384             // A 8KB + B 8KB per stage; 4 stages = 64KB
#define SMEM_TOT (4 * STAGE_B)

typedef __nv_bfloat16 bf16;
typedef __nv_bfloat162 bf162;

__device__ bf16 b_A1[NS*DD],  b_A2[NS*DD];
__device__ bf16 b_A1c[NS*DD], b_A2c[NS*DD];
__device__ bf16 b_U1[NS*DD],  b_U2[NS*DD],  b_U1c[NS*DD], b_U2c[NS*DD];
__device__ bf16 b_H1[NS*DD],  b_H2[NS*DD],  b_H1c[NS*DD], b_H2c[NS*DD];
__device__ bf16 b_W1[DD*DD], b_W2[DD*DD], b_W3[DD*DD], b_W4[DD*DD];
__device__ float g_r11[2*NS], g_r22[2*NS], g_r12[2*NS], g_c12[2*NS];
__device__ float g_d11[2*NS], g_d22[2*NS], g_d12[2*NS];
__device__ float g_loss[2];

// ---------------- primitives -------------------------------------------------
__device__ __forceinline__ void ldm_x4(uint32_t& r0, uint32_t& r1, uint32_t& r2,
                                       uint32_t& r3, uint32_t a)
{
    asm volatile("ldmatrix.sync.aligned.m8n8.x4.shared.b16 {%0,%1,%2,%3}, [%4];"
                 : "=r"(r0), "=r"(r1), "=r"(r2), "=r"(r3) : "r"(a));
}
__device__ __forceinline__ void mma16816(float* c, const uint32_t* a, const uint32_t* b)
{
    asm volatile("mma.sync.aligned.m16n8k16.row.col.f32.bf16.bf16.f32 "
                 "{%0,%1,%2,%3}, {%4,%5,%6,%7}, {%8,%9}, {%0,%1,%2,%3};"
                 : "+f"(c[0]), "+f"(c[1]), "+f"(c[2]), "+f"(c[3])
                 : "r"(a[0]), "r"(a[1]), "r"(a[2]), "r"(a[3]), "r"(b[0]), "r"(b[1]));
}
__device__ __forceinline__ void cpa16(uint32_t dst, const void* src)
{ asm volatile("cp.async.cg.shared.global [%0], [%1], 16;" :: "r"(dst), "l"(src)); }
#define CP_COMMIT() asm volatile("cp.async.commit_group;" ::: "memory")
#define CP_WAIT2()  asm volatile("cp.async.wait_group 2;" ::: "memory")
#define CP_WAIT1()  asm volatile("cp.async.wait_group 1;" ::: "memory")
#define CP_WAIT0()  asm volatile("cp.async.wait_group 0;" ::: "memory")
__device__ __forceinline__ uint32_t swz(int row, int q)
{ return (uint32_t)(row * 64 + ((q ^ ((row >> 1) & 3)) << 4)); }

// ---------------- mainloop: 128x128 fp32 tile of A·B^T, K=1024 --------------
// Warp grid 2x4; warp tile 64x32; acc[ti][tj][4]. 4 stages, chunk loop
// unrolled x4 (literal stage offsets). K-chunk = 32 elems (64B rows).
__device__ __forceinline__ void mma_mainloop(const bf16* __restrict__ A,
    const bf16* __restrict__ B, int m0, int n0, char* sm, float acc[4][4][4])
{
    const int tid = threadIdx.x, lane = tid & 31, wid = tid >> 5;
    const int wm = wid >> 2, wn = wid & 3;
    const int r = lane & 7, tsel = lane >> 3;
    const int a_row = ((tsel & 1) << 3) + r, a_col = (tsel >> 1) << 3;
    const int b_row = ((tsel >> 1) << 3) + r, b_col = (tsel & 1) << 3;

    const char *sp0, *sp1, *sp2, *sp3;
    uint32_t dof0, dof1, dof2, dof3;
    const uint32_t smb = (uint32_t)__cvta_generic_to_shared(sm);
    {
        const char* s[4]; uint32_t d[4];
        #pragma unroll
        for (int it = 0; it < 4; it++) {
            int id = it * 256 + tid;
            int half = id >> 9, rem = id & 511;
            int row = rem >> 2, q = rem & 3;
            s[it] = (const char*)((half ? B + (size_t)(n0 + row) * DD
                                        : A + (size_t)(m0 + row) * DD) + q * 8);
            d[it] = smb + half * 8192u + swz(row, q);
        }
        sp0 = s[0]; sp1 = s[1]; sp2 = s[2]; sp3 = s[3];
        dof0 = d[0]; dof1 = d[1]; dof2 = d[2]; dof3 = d[3];
    }

    #pragma unroll
    for (int i = 0; i < 4; i++)
        #pragma unroll
        for (int j = 0; j < 4; j++)
            #pragma unroll
            for (int p = 0; p < 4; p++) acc[i][j][p] = 0.f;

    // prologue: chunks 0,1,2 -> stages 0,1,2
    cpa16(dof0, sp0); cpa16(dof1, sp1); cpa16(dof2, sp2); cpa16(dof3, sp3);
    CP_COMMIT();
    cpa16(dof0 + STAGE_B, sp0 + 64); cpa16(dof1 + STAGE_B, sp1 + 64);
    cpa16(dof2 + STAGE_B, sp2 + 64); cpa16(dof3 + STAGE_B, sp3 + 64);
    CP_COMMIT();
    cpa16(dof0 + 2*STAGE_B, sp0 + 128); cpa16(dof1 + 2*STAGE_B, sp1 + 128);
    cpa16(dof2 + 2*STAGE_B, sp2 + 128); cpa16(dof3 + 2*STAGE_B, sp3 + 128);
    CP_COMMIT();
    sp0 += 192; sp1 += 192; sp2 += 192; sp3 += 192;   // -> chunk 3 data

    auto compute = [&](uint32_t cs) {
        const uint32_t sA = smb + cs;
        const uint32_t sB = sA + 8192u;
        #pragma unroll
        for (int ks = 0; ks < 32; ks += 16) {
            uint32_t a[4][4], b[4][2];
            #pragma unroll
            for (int ti = 0; ti < 4; ti++)
                ldm_x4(a[ti][0], a[ti][1], a[ti][2], a[ti][3],
                       sA + swz(wm*64 + ti*16 + a_row, (ks + a_col) >> 3));
            #pragma unroll
            for (int pp = 0; pp < 2; pp++)
                ldm_x4(b[2*pp][0], b[2*pp][1], b[2*pp+1][0], b[2*pp+1][1],
                       sB + swz(wn*32 + pp*16 + b_row, (ks + b_col) >> 3));
            #pragma unroll
            for (int ti = 0; ti < 4; ti++)
                #pragma unroll
                for (int tj = 0; tj < 4; tj++)
                    mma16816(acc[ti][tj], a[ti], b[tj]);
        }
    };

    // step: wait<=2, sync, prefetch chunk c+3 into stage poff, compute stage cs
    #define PIPE_STEP(cs, poff)                                                  \
        do {                                                                     \
            CP_WAIT2();                                                          \
            __syncthreads();                                                     \
            cpa16(dof0 + (poff), sp0); cpa16(dof1 + (poff), sp1);                \
            cpa16(dof2 + (poff), sp2); cpa16(dof3 + (poff), sp3);                \
            CP_COMMIT();                                                         \
            sp0 += 64; sp1 += 64; sp2 += 64; sp3 += 64;                          \
            compute(cs);                                                         \
        } while (0)

    #pragma unroll 1
    for (int cb = 0; cb < 28; cb += 4) {          // c = 0..27, prefetch 3..30
        PIPE_STEP(0u,          3u*STAGE_B);
        PIPE_STEP(STAGE_B,     0u);
        PIPE_STEP(2u*STAGE_B,  STAGE_B);
        PIPE_STEP(3u*STAGE_B,  2u*STAGE_B);
    }
    #undef PIPE_STEP
    // c=28: prefetch chunk 31 -> stage 3, compute stage 0
    CP_WAIT2(); __syncthreads();
    cpa16(dof0 + 3u*STAGE_B, sp0); cpa16(dof1 + 3u*STAGE_B, sp1);
    cpa16(dof2 + 3u*STAGE_B, sp2); cpa16(dof3 + 3u*STAGE_B, sp3);
    CP_COMMIT();
    compute(0u);
    CP_WAIT2(); __syncthreads(); compute(STAGE_B);       // c=29
    CP_WAIT1(); __syncthreads(); compute(2u*STAGE_B);    // c=30
    CP_WAIT0(); __syncthreads(); compute(3u*STAGE_B);    // c=31
}

// ---------------- projection GEMM body --------------------------------------
template<int MODE>
__device__ __forceinline__ void gemm_body(const bf16* __restrict__ A,
    const bf16* __restrict__ W, const float* __restrict__ bias, bf16* __restrict__ C)
{
    extern __shared__ __align__(16) char sm[];
    const int m0 = blockIdx.y * 128, n0 = blockIdx.x * 128;
    const int lane = threadIdx.x & 31, wid = threadIdx.x >> 5;
    const int wm = wid >> 2, wn = wid & 3;
    const int grp = lane >> 2, qid = lane & 3;

    float acc[4][4][4];
    mma_mainloop(A, W, m0, n0, sm, acc);

    #pragma unroll
    for (int tj = 0; tj < 4; tj++) {
        int gc = n0 + wn*32 + tj*8 + qid*2;
        float bv0 = bias[gc], bv1 = bias[gc+1];
        #pragma unroll
        for (int ti = 0; ti < 4; ti++)
            #pragma unroll
            for (int h = 0; h < 2; h++) {
                int gr = m0 + wm*64 + ti*16 + h*8 + grp;
                float v0 = acc[ti][tj][h*2+0] + bv0;
                float v1 = acc[ti][tj][h*2+1] + bv1;
                if (MODE == 1) {
                    v0 = v0 > 0.f ? v0 : expm1f(v0);
                    v1 = v1 > 0.f ? v1 : expm1f(v1);
                }
                *(bf162*)(C + (size_t)gr * DD + gc) = __floats2bfloat162_rn(v0, v1);
            }
    }
}

__global__ __launch_bounds__(256, 2) void proj1_all(const float* b1, const float* b3)
{
    int z = blockIdx.z;
    const bf16 *A, *W; bf16* C;
    if (z == 0)      { A = b_A1;  W = b_W1; C = b_U1;  }
    else if (z == 1) { A = b_A2;  W = b_W1; C = b_U2;  }
    else if (z == 2) { A = b_A1c; W = b_W3; C = b_U1c; }
    else             { A = b_A2c; W = b_W3; C = b_U2c; }
    gemm_body<1>(A, W, (z < 2) ? b1 : b3, C);
}
__global__ __launch_bounds__(256, 2) void proj2_all(const float* b2, const float* b4)
{
    int z = blockIdx.z;
    const bf16 *A, *W; bf16* C;
    if (z == 0)      { A = b_U1;  W = b_W2; C = b_H1;  }
    else if (z == 1) { A = b_U2;  W = b_W2; C = b_H2;  }
    else if (z == 2) { A = b_U1c; W = b_W4; C = b_H1c; }
    else             { A = b_U2c; W = b_W4; C = b_H2c; }
    gemm_body<0>(A, W, (z < 2) ? b2 : b4, C);
}

// ---------------- fused similarity: all 6 matrices in one launch -------------
__global__ __launch_bounds__(256, 2) void sim_all()
{
    const int z = blockIdx.z;
    const int v = z / 3, m = z % 3;
    const bool SYM = (m != 2);
    const int bi = blockIdx.y;
    const int bj = SYM ? (bi + blockIdx.x) : blockIdx.x;
    if (SYM && bj >= 64) return;

    const bf16 *A, *B;
    float *rs, *cs, *dg;
    if (v == 0) {
        A = (m == 1) ? b_H2 : b_H1;
        B = (m == 0) ? b_H1 : b_H2;
        rs = (m == 0) ? g_r11 : (m == 1) ? g_r22 : g_r12;
        dg = (m == 0) ? g_d11 : (m == 1) ? g_d22 : g_d12;
    } else {
        A = (m == 1) ? b_H2c : b_H1c;
        B = (m == 0) ? b_H1c : b_H2c;
        rs = ((m == 0) ? g_r11 : (m == 1) ? g_r22 : g_r12) + NS;
        dg = ((m == 0) ? g_d11 : (m == 1) ? g_d22 : g_d12) + NS;
    }
    cs = SYM ? rs : (g_c12 + v*NS);

    extern __shared__ __align__(16) char sm[];
    const int m0 = bi * 128, n0 = bj * 128;
    const int lane = threadIdx.x & 31, wid = threadIdx.x >> 5;
    const int wm = wid >> 2, wn = wid & 3;
    const int grp = lane >> 2, qid = lane & 3;
    const bool diag = (bi == bj);
    const bool doCols = (!SYM) || (bj > bi);

    float acc[4][4][4];
    mma_mainloop(A, B, m0, n0, sm, acc);

    #pragma unroll
    for (int ti = 0; ti < 4; ti++)
        #pragma unroll
        for (int h = 0; h < 2; h++) {
            int gr = m0 + wm*64 + ti*16 + h*8 + grp;
            float rsum = 0.f;
            #pragma unroll
            for (int tj = 0; tj < 4; tj++) {
                int gc = n0 + wn*32 + tj*8 + qid*2;
                float e0 = __expf(2.f * acc[ti][tj][h*2+0]);
                float e1 = __expf(2.f * acc[ti][tj][h*2+1]);
                acc[ti][tj][h*2+0] = e0;
                acc[ti][tj][h*2+1] = e1;
                rsum += e0 + e1;
                if (diag) {
                    if (gr == gc)     dg[gr] = e0;
                    if (gr == gc + 1) dg[gr] = e1;
                }
            }
            rsum += __shfl_down_sync(0xffffffffu, rsum, 2, 4);
            rsum += __shfl_down_sync(0xffffffffu, rsum, 1, 4);
            if (qid == 0) atomicAdd(&rs[gr], rsum);
        }

    if (doCols) {
        #pragma unroll
        for (int tj = 0; tj < 4; tj++) {
            float c0 = 0.f, c1 = 0.f;
            #pragma unroll
            for (int ti = 0; ti < 4; ti++) {
                c0 += acc[ti][tj][0] + acc[ti][tj][2];
                c1 += acc[ti][tj][1] + acc[ti][tj][3];
            }
            #pragma unroll
            for (int o = 4; o <= 16; o <<= 1) {
                c0 += __shfl_xor_sync(0xffffffffu, c0, o);
                c1 += __shfl_xor_sync(0xffffffffu, c1, o);
            }
            if (grp == 0) {
                int gc = n0 + wn*32 + tj*8 + qid*2;
                atomicAdd(&cs[gc],   c0);
                atomicAdd(&cs[gc+1], c1);
            }
        }
    }
}

// ---------------- aux kernels (z-fused) --------------------------------------
__global__ void conv_all(const float* ta, const float* tb,
                         const float* W1, const float* W2,
                         const float* W3, const float* W4)
{
    int z = blockIdx.z;
    int nblk = (z < 2) ? 2048 : 256;
    if (blockIdx.x >= (unsigned)nblk) return;
    const float* s; bf16* d;
    if (z == 0)      { s = ta; d = b_A1; }
    else if (z == 1) { s = tb; d = b_A2; }
    else if (z == 2) { s = W1; d = b_W1; }
    else if (z == 3) { s = W2; d = b_W2; }
    else if (z == 4) { s = W3; d = b_W3; }
    else             { s = W4; d = b_W4; }
    int i = blockIdx.x * blockDim.x + threadIdx.x;
    int st = nblk * 256;
    float4 v0 = ((const float4*)s)[i];
    float4 v1 = ((const float4*)s)[i + st];
    float4 v2 = ((const float4*)s)[i + 2*st];
    float4 v3 = ((const float4*)s)[i + 3*st];
    ((bf162*)d)[(i)*2+0]      = __floats2bfloat162_rn(v0.x, v0.y);
    ((bf162*)d)[(i)*2+1]      = __floats2bfloat162_rn(v0.z, v0.w);
    ((bf162*)d)[(i+st)*2+0]   = __floats2bfloat162_rn(v1.x, v1.y);
    ((bf162*)d)[(i+st)*2+1]   = __floats2bfloat162_rn(v1.z, v1.w);
    ((bf162*)d)[(i+2*st)*2+0] = __floats2bfloat162_rn(v2.x, v2.y);
    ((bf162*)d)[(i+2*st)*2+1] = __floats2bfloat162_rn(v2.z, v2.w);
    ((bf162*)d)[(i+3*st)*2+0] = __floats2bfloat162_rn(v3.x, v3.y);
    ((bf162*)d)[(i+3*st)*2+1] = __floats2bfloat162_rn(v3.z, v3.w);
}

__global__ __launch_bounds__(256) void trans_all(const float* ta, const float* tb)
{
    const float* in = blockIdx.z ? tb : ta;
    bf16* out = blockIdx.z ? b_A2c : b_A1c;
    __shared__ float t[32][33];
    const float* s = in  + (size_t)blockIdx.x * 1024;
    bf16*        d = out + (size_t)blockIdx.x * 1024;
    for (int i = threadIdx.x; i < 1024; i += 256) t[i >> 5][i & 31] = s[i];
    __syncthreads();
    for (int i = threadIdx.x; i < 1024; i += 256)
        d[i] = __float2bfloat16(t[i & 31][i >> 5]);
}

__global__ __launch_bounds__(256) void norm_all()
{
    bf16* H = (blockIdx.z == 0) ? b_H1 : (blockIdx.z == 1) ? b_H2
            : (blockIdx.z == 2) ? b_H1c : b_H2c;
    int row = blockIdx.x;
    uint2* p = (uint2*)(H + (size_t)row * DD) + threadIdx.x;
    uint2 raw = *p;
    bf162 v0 = *(bf162*)&raw.x;
    bf162 v1 = *(bf162*)&raw.y;
    float a = __bfloat162float(v0.x), b = __bfloat162float(v0.y);
    float c = __bfloat162float(v1.x), d = __bfloat162float(v1.y);
    float s = a*a + b*b + c*c + d*d;
    #pragma unroll
    for (int o = 16; o; o >>= 1) s += __shfl_xor_sync(0xffffffffu, s, o);
    __shared__ float red[8];
    int lane = threadIdx.x & 31, w = threadIdx.x >> 5;
    if (lane == 0) red[w] = s;
    __syncthreads();
    __shared__ float invn;
    if (threadIdx.x == 0) {
        float t = 0.f;
        #pragma unroll
        for (int i = 0; i < 8; i++) t += red[i];
        invn = rsqrtf(t);
    }
    __syncthreads();
    float iv = invn;
    uint2 ow;
    *(bf162*)&ow.x = __floats2bfloat162_rn(a*iv, b*iv);
    *(bf162*)&ow.y = __floats2bfloat162_rn(c*iv, d*iv);
    *p = ow;
}

__global__ void zero_stats()
{
    int i = blockIdx.x * blockDim.x + threadIdx.x;
    if (i < 2*NS) { g_r11[i] = 0.f; g_r22[i] = 0.f; g_r12[i] = 0.f; g_c12[i] = 0.f; }
    if (i < 2) g_loss[i] = 0.f;
}

__global__ void loss_all()
{
    int v = blockIdx.z;
    int i = blockIdx.x * blockDim.x + threadIdx.x;
    float val = 0.f;
    if (i < NS) {
        int k = v*NS + i;
        float ld = logf(g_d12[k]);
        float l1 = logf(g_r11[k] + g_r12[k] - g_d11[k]) - ld;
        float l2 = logf(g_r22[k] + g_c12[k] - g_d22[k]) - ld;
        val = 0.5f * (l1 + l2) * (1.0f / NS);
    }
    #pragma unroll
    for (int o = 16; o; o >>= 1) val += __shfl_down_sync(0xffffffffu, val, o);
    if ((threadIdx.x & 31) == 0) atomicAdd(&g_loss[v], val);
}

__global__ void finalize_k(const float* __restrict__ w_r1, float* __restrict__ out)
{
    float w = fminf(fmaxf(w_r1[0], 0.f), 1.f);
    out[0] = w * g_loss[0] + (1.f - w) * g_loss[1];
}

// ----------------------------------------------------------------------------
extern "C" void kernel_launch(void* const* d_in, const int* in_sizes, int n_in,
                              void* d_out, int out_size)
{
    const float* ta   = (const float*)d_in[0];
    const float* tb   = (const float*)d_in[1];
    const float* W1   = (const float*)d_in[2];
    const float* b1   = (const float*)d_in[3];
    const float* W2   = (const float*)d_in[4];
    const float* b2   = (const float*)d_in[5];
    const float* W3   = (const float*)d_in[6];
    const float* b3   = (const float*)d_in[7];
    const float* W4   = (const float*)d_in[8];
    const float* b4   = (const float*)d_in[9];
    const float* w_r1 = (const float*)d_in[10];
    float* out = (float*)d_out;

    // opt-in >48KB dynamic smem (idempotent; not a stream op — capture-safe)
    cudaFuncSetAttribute(proj1_all, cudaFuncAttributeMaxDynamicSharedMemorySize, SMEM_TOT);
    cudaFuncSetAttribute(proj2_all, cudaFuncAttributeMaxDynamicSharedMemorySize, SMEM_TOT);
    cudaFuncSetAttribute(sim_all,   cudaFuncAttributeMaxDynamicSharedMemorySize, SMEM_TOT);

    conv_all <<<dim3(2048, 1, 6), 256>>>(ta, tb, W1, W2, W3, W4);
    trans_all<<<dim3(NS, 1, 2), 256>>>(ta, tb);
    zero_stats<<<(2*NS + 255)/256, 256>>>();
    proj1_all<<<dim3(8, 64, 4), 256, SMEM_TOT>>>(b1, b3);
    proj2_all<<<dim3(8, 64, 4), 256, SMEM_TOT>>>(b2, b4);
    norm_all <<<dim3(NS, 1, 4), 256>>>();
    sim_all  <<<dim3(64, 64, 6), 256, SMEM_TOT>>>();
    loss_all <<<dim3(32, 1, 2), 256>>>();
    finalize_k<<<1, 1>>>(w_r1, out);
}

// round 16
// speedup vs baseline: 1.0494x; 1.0494x over previous
#include <cuda_runtime.h>
#include <cuda_bf16.h>
#include <math.h>
#include <stdint.h>

// TContrastive: bf16 mma.sync 128x128 tiles @ 2 CTAs/SM, cp.async 3-stage
// pipeline, K-chunk 64 (128B SW128 rows), 96KB dynamic smem, z-fused launches.

#define NS 8192
#define DD 1024
#define STAGE_B 32768             // A 16KB + B 16KB per stage; 3 stages = 96KB
#define SMEM_TOT (3 * STAGE_B)

typedef __nv_bfloat16 bf16;
typedef __nv_bfloat162 bf162;

__device__ bf16 b_A1[NS*DD],  b_A2[NS*DD];
__device__ bf16 b_A1c[NS*DD], b_A2c[NS*DD];
__device__ bf16 b_U1[NS*DD],  b_U2[NS*DD],  b_U1c[NS*DD], b_U2c[NS*DD];
__device__ bf16 b_H1[NS*DD],  b_H2[NS*DD],  b_H1c[NS*DD], b_H2c[NS*DD];
__device__ bf16 b_W1[DD*DD], b_W2[DD*DD], b_W3[DD*DD], b_W4[DD*DD];
__device__ float g_r11[2*NS], g_r22[2*NS], g_r12[2*NS], g_c12[2*NS];
__device__ float g_d11[2*NS], g_d22[2*NS], g_d12[2*NS];
__device__ float g_loss[2];

// ---------------- primitives -------------------------------------------------
__device__ __forceinline__ void ldm_x4(uint32_t& r0, uint32_t& r1, uint32_t& r2,
                                       uint32_t& r3, uint32_t a)
{
    asm volatile("ldmatrix.sync.aligned.m8n8.x4.shared.b16 {%0,%1,%2,%3}, [%4];"
                 : "=r"(r0), "=r"(r1), "=r"(r2), "=r"(r3) : "r"(a));
}
__device__ __forceinline__ void mma16816(float* c, const uint32_t* a, const uint32_t* b)
{
    asm volatile("mma.sync.aligned.m16n8k16.row.col.f32.bf16.bf16.f32 "
                 "{%0,%1,%2,%3}, {%4,%5,%6,%7}, {%8,%9}, {%0,%1,%2,%3};"
                 : "+f"(c[0]), "+f"(c[1]), "+f"(c[2]), "+f"(c[3])
                 : "r"(a[0]), "r"(a[1]), "r"(a[2]), "r"(a[3]), "r"(b[0]), "r"(b[1]));
}
__device__ __forceinline__ void cpa16(uint32_t dst, const void* src)
{ asm volatile("cp.async.cg.shared.global [%0], [%1], 16;" :: "r"(dst), "l"(src)); }
#define CP_COMMIT() asm volatile("cp.async.commit_group;" ::: "memory")
#define CP_WAIT1()  asm volatile("cp.async.wait_group 1;" ::: "memory")
#define CP_WAIT0()  asm volatile("cp.async.wait_group 0;" ::: "memory")

// SW128 swizzle for 128B rows: byte = row*128 + ((q ^ (row&7)) << 4), q = 16B col
__device__ __forceinline__ uint32_t swz128(int row, int q)
{ return (uint32_t)(row * 128 + ((q ^ (row & 7)) << 4)); }

// ---------------- mainloop: 128x128 fp32 tile of A·B^T, K=1024 --------------
// Warp grid 2x4; warp tile 64x32; acc[ti][tj][4]. K-chunk 64 elems (128B rows),
// 16 chunks, 3 stages (literal offsets), wait_group 1.
__device__ __forceinline__ void mma_mainloop(const bf16* __restrict__ A,
    const bf16* __restrict__ B, int m0, int n0, char* sm, float acc[4][4][4])
{
    const int tid = threadIdx.x, lane = tid & 31, wid = tid >> 5;
    const int wm = wid >> 2, wn = wid & 3;
    const int r = lane & 7, tsel = lane >> 3;
    const int a_row = ((tsel & 1) << 3) + r, a_col = (tsel >> 1) << 3;
    const int b_row = ((tsel >> 1) << 3) + r, b_col = (tsel & 1) << 3;

    const uint32_t smb = (uint32_t)__cvta_generic_to_shared(sm);
    // copy: thread covers rows cr+32k (k=0..3) of A and of B, 16B col cq
    const int cr = tid >> 3, cq = tid & 7;
    const char* spA = (const char*)(A + (size_t)(m0 + cr) * DD) + cq * 16;
    const char* spB = (const char*)(B + (size_t)(n0 + cr) * DD) + cq * 16;
    const uint32_t dA = smb + swz128(cr, cq);          // +4096 per 32 rows
    const uint32_t dB = dA + 16384u;

    #pragma unroll
    for (int i = 0; i < 4; i++)
        #pragma unroll
        for (int j = 0; j < 4; j++)
            #pragma unroll
            for (int p = 0; p < 4; p++) acc[i][j][p] = 0.f;

    // chunk copy at stage offset soff (8 x 16B per thread), then commit
    #define DO_COPY(soff)                                                        \
        do {                                                                     \
            cpa16(dA + (soff),          spA);                                    \
            cpa16(dA + (soff) + 4096u,  spA + 65536);                            \
            cpa16(dA + (soff) + 8192u,  spA + 131072);                           \
            cpa16(dA + (soff) + 12288u, spA + 196608);                           \
            cpa16(dB + (soff),          spB);                                    \
            cpa16(dB + (soff) + 4096u,  spB + 65536);                            \
            cpa16(dB + (soff) + 8192u,  spB + 131072);                           \
            cpa16(dB + (soff) + 12288u, spB + 196608);                           \
            CP_COMMIT();                                                         \
            spA += 128; spB += 128;                                              \
        } while (0)

    // prologue: chunks 0,1 -> stages 0,1
    DO_COPY(0u);
    DO_COPY((uint32_t)STAGE_B);

    auto compute = [&](uint32_t cs) {
        const uint32_t sA = smb + cs;
        const uint32_t sB = sA + 16384u;
        #pragma unroll
        for (int ks = 0; ks < 64; ks += 16) {
            uint32_t a[4][4], b[4][2];
            int qa = (ks + a_col) >> 3, qb = (ks + b_col) >> 3;
            #pragma unroll
            for (int ti = 0; ti < 4; ti++) {
                int rr = wm*64 + ti*16 + a_row;
                ldm_x4(a[ti][0], a[ti][1], a[ti][2], a[ti][3], sA + swz128(rr, qa));
            }
            #pragma unroll
            for (int pp = 0; pp < 2; pp++) {
                int rr = wn*32 + pp*16 + b_row;
                ldm_x4(b[2*pp][0], b[2*pp][1], b[2*pp+1][0], b[2*pp+1][1],
                       sB + swz128(rr, qb));
            }
            #pragma unroll
            for (int ti = 0; ti < 4; ti++)
                #pragma unroll
                for (int tj = 0; tj < 4; tj++)
                    mma16816(acc[ti][tj], a[ti], b[tj]);
        }
    };

    // step: wait<=1, sync, prefetch chunk c+2 into stage poff, compute stage cs
    #define PIPE_STEP(cs, poff)                                                  \
        do {                                                                     \
            CP_WAIT1();                                                          \
            __syncthreads();                                                     \
            DO_COPY(poff);                                                       \
            compute(cs);                                                         \
        } while (0)

    #pragma unroll 1
    for (int cb = 0; cb < 12; cb += 3) {          // c = 0..11, prefetch 2..13
        PIPE_STEP(0u,                  2u*STAGE_B);
        PIPE_STEP((uint32_t)STAGE_B,   0u);
        PIPE_STEP(2u*STAGE_B,          (uint32_t)STAGE_B);
    }
    PIPE_STEP(0u,                2u*STAGE_B);     // c=12, prefetch 14
    PIPE_STEP((uint32_t)STAGE_B, 0u);             // c=13, prefetch 15
    #undef PIPE_STEP
    #undef DO_COPY
    CP_WAIT1(); __syncthreads(); compute(2u*STAGE_B);   // c=14
    CP_WAIT0(); __syncthreads(); compute(0u);           // c=15
}

// ---------------- projection GEMM body --------------------------------------
template<int MODE>
__device__ __forceinline__ void gemm_body(const bf16* __restrict__ A,
    const bf16* __restrict__ W, const float* __restrict__ bias, bf16* __restrict__ C)
{
    extern __shared__ __align__(16) char sm[];
    const int m0 = blockIdx.y * 128, n0 = blockIdx.x * 128;
    const int lane = threadIdx.x & 31, wid = threadIdx.x >> 5;
    const int wm = wid >> 2, wn = wid & 3;
    const int grp = lane >> 2, qid = lane & 3;

    float acc[4][4][4];
    mma_mainloop(A, W, m0, n0, sm, acc);

    #pragma unroll
    for (int tj = 0; tj < 4; tj++) {
        int gc = n0 + wn*32 + tj*8 + qid*2;
        float bv0 = bias[gc], bv1 = bias[gc+1];
        #pragma unroll
        for (int ti = 0; ti < 4; ti++)
            #pragma unroll
            for (int h = 0; h < 2; h++) {
                int gr = m0 + wm*64 + ti*16 + h*8 + grp;
                float v0 = acc[ti][tj][h*2+0] + bv0;
                float v1 = acc[ti][tj][h*2+1] + bv1;
                if (MODE == 1) {
                    v0 = v0 > 0.f ? v0 : expm1f(v0);
                    v1 = v1 > 0.f ? v1 : expm1f(v1);
                }
                *(bf162*)(C + (size_t)gr * DD + gc) = __floats2bfloat162_rn(v0, v1);
            }
    }
}

__global__ __launch_bounds__(256, 2) void proj1_all(const float* b1, const float* b3)
{
    int z = blockIdx.z;
    const bf16 *A, *W; bf16* C;
    if (z == 0)      { A = b_A1;  W = b_W1; C = b_U1;  }
    else if (z == 1) { A = b_A2;  W = b_W1; C = b_U2;  }
    else if (z == 2) { A = b_A1c; W = b_W3; C = b_U1c; }
    else             { A = b_A2c; W = b_W3; C = b_U2c; }
    gemm_body<1>(A, W, (z < 2) ? b1 : b3, C);
}
__global__ __launch_bounds__(256, 2) void proj2_all(const float* b2, const float* b4)
{
    int z = blockIdx.z;
    const bf16 *A, *W; bf16* C;
    if (z == 0)      { A = b_U1;  W = b_W2; C = b_H1;  }
    else if (z == 1) { A = b_U2;  W = b_W2; C = b_H2;  }
    else if (z == 2) { A = b_U1c; W = b_W4; C = b_H1c; }
    else             { A = b_U2c; W = b_W4; C = b_H2c; }
    gemm_body<0>(A, W, (z < 2) ? b2 : b4, C);
}

// ---------------- fused similarity: all 6 matrices in one launch -------------
__global__ __launch_bounds__(256, 2) void sim_all()
{
    const int z = blockIdx.z;
    const int v = z / 3, m = z % 3;
    const bool SYM = (m != 2);
    const int bi = blockIdx.y;
    const int bj = SYM ? (bi + blockIdx.x) : blockIdx.x;
    if (SYM && bj >= 64) return;

    const bf16 *A, *B;
    float *rs, *cs, *dg;
    if (v == 0) {
        A = (m == 1) ? b_H2 : b_H1;
        B = (m == 0) ? b_H1 : b_H2;
        rs = (m == 0) ? g_r11 : (m == 1) ? g_r22 : g_r12;
        dg = (m == 0) ? g_d11 : (m == 1) ? g_d22 : g_d12;
    } else {
        A = (m == 1) ? b_H2c : b_H1c;
        B = (m == 0) ? b_H1c : b_H2c;
        rs = ((m == 0) ? g_r11 : (m == 1) ? g_r22 : g_r12) + NS;
        dg = ((m == 0) ? g_d11 : (m == 1) ? g_d22 : g_d12) + NS;
    }
    cs = SYM ? rs : (g_c12 + v*NS);

    extern __shared__ __align__(16) char sm[];
    const int m0 = bi * 128, n0 = bj * 128;
    const int lane = threadIdx.x & 31, wid = threadIdx.x >> 5;
    const int wm = wid >> 2, wn = wid & 3;
    const int grp = lane >> 2, qid = lane & 3;
    const bool diag = (bi == bj);
    const bool doCols = (!SYM) || (bj > bi);

    float acc[4][4][4];
    mma_mainloop(A, B, m0, n0, sm, acc);

    #pragma unroll
    for (int ti = 0; ti < 4; ti++)
        #pragma unroll
        for (int h = 0; h < 2; h++) {
            int gr = m0 + wm*64 + ti*16 + h*8 + grp;
            float rsum = 0.f;
            #pragma unroll
            for (int tj = 0; tj < 4; tj++) {
                int gc = n0 + wn*32 + tj*8 + qid*2;
                float e0 = __expf(2.f * acc[ti][tj][h*2+0]);
                float e1 = __expf(2.f * acc[ti][tj][h*2+1]);
                acc[ti][tj][h*2+0] = e0;
                acc[ti][tj][h*2+1] = e1;
                rsum += e0 + e1;
                if (diag) {
                    if (gr == gc)     dg[gr] = e0;
                    if (gr == gc + 1) dg[gr] = e1;
                }
            }
            rsum += __shfl_down_sync(0xffffffffu, rsum, 2, 4);
            rsum += __shfl_down_sync(0xffffffffu, rsum, 1, 4);
            if (qid == 0) atomicAdd(&rs[gr], rsum);
        }

    if (doCols) {
        #pragma unroll
        for (int tj = 0; tj < 4; tj++) {
            float c0 = 0.f, c1 = 0.f;
            #pragma unroll
            for (int ti = 0; ti < 4; ti++) {
                c0 += acc[ti][tj][0] + acc[ti][tj][2];
                c1 += acc[ti][tj][1] + acc[ti][tj][3];
            }
            #pragma unroll
            for (int o = 4; o <= 16; o <<= 1) {
                c0 += __shfl_xor_sync(0xffffffffu, c0, o);
                c1 += __shfl_xor_sync(0xffffffffu, c1, o);
            }
            if (grp == 0) {
                int gc = n0 + wn*32 + tj*8 + qid*2;
                atomicAdd(&cs[gc],   c0);
                atomicAdd(&cs[gc+1], c1);
            }
        }
    }
}

// ---------------- aux kernels (z-fused) --------------------------------------
__global__ void conv_all(const float* ta, const float* tb,
                         const float* W1, const float* W2,
                         const float* W3, const float* W4)
{
    int z = blockIdx.z;
    int nblk = (z < 2) ? 2048 : 256;
    if (blockIdx.x >= (unsigned)nblk) return;
    const float* s; bf16* d;
    if (z == 0)      { s = ta; d = b_A1; }
    else if (z == 1) { s = tb; d = b_A2; }
    else if (z == 2) { s = W1; d = b_W1; }
    else if (z == 3) { s = W2; d = b_W2; }
    else if (z == 4) { s = W3; d = b_W3; }
    else             { s = W4; d = b_W4; }
    int i = blockIdx.x * blockDim.x + threadIdx.x;
    int st = nblk * 256;
    float4 v0 = ((const float4*)s)[i];
    float4 v1 = ((const float4*)s)[i + st];
    float4 v2 = ((const float4*)s)[i + 2*st];
    float4 v3 = ((const float4*)s)[i + 3*st];
    ((bf162*)d)[(i)*2+0]      = __floats2bfloat162_rn(v0.x, v0.y);
    ((bf162*)d)[(i)*2+1]      = __floats2bfloat162_rn(v0.z, v0.w);
    ((bf162*)d)[(i+st)*2+0]   = __floats2bfloat162_rn(v1.x, v1.y);
    ((bf162*)d)[(i+st)*2+1]   = __floats2bfloat162_rn(v1.z, v1.w);
    ((bf162*)d)[(i+2*st)*2+0] = __floats2bfloat162_rn(v2.x, v2.y);
    ((bf162*)d)[(i+2*st)*2+1] = __floats2bfloat162_rn(v2.z, v2.w);
    ((bf162*)d)[(i+3*st)*2+0] = __floats2bfloat162_rn(v3.x, v3.y);
    ((bf162*)d)[(i+3*st)*2+1] = __floats2bfloat162_rn(v3.z, v3.w);
}

__global__ __launch_bounds__(256) void trans_all(const float* ta, const float* tb)
{
    const float* in = blockIdx.z ? tb : ta;
    bf16* out = blockIdx.z ? b_A2c : b_A1c;
    __shared__ float t[32][33];
    const float* s = in  + (size_t)blockIdx.x * 1024;
    bf16*        d = out + (size_t)blockIdx.x * 1024;
    for (int i = threadIdx.x; i < 1024; i += 256) t[i >> 5][i & 31] = s[i];
    __syncthreads();
    for (int i = threadIdx.x; i < 1024; i += 256)
        d[i] = __float2bfloat16(t[i & 31][i >> 5]);
}

__global__ __launch_bounds__(256) void norm_all()
{
    bf16* H = (blockIdx.z == 0) ? b_H1 : (blockIdx.z == 1) ? b_H2
            : (blockIdx.z == 2) ? b_H1c : b_H2c;
    int row = blockIdx.x;
    uint2* p = (uint2*)(H + (size_t)row * DD) + threadIdx.x;
    uint2 raw = *p;
    bf162 v0 = *(bf162*)&raw.x;
    bf162 v1 = *(bf162*)&raw.y;
    float a = __bfloat162float(v0.x), b = __bfloat162float(v0.y);
    float c = __bfloat162float(v1.x), d = __bfloat162float(v1.y);
    float s = a*a + b*b + c*c + d*d;
    #pragma unroll
    for (int o = 16; o; o >>= 1) s += __shfl_xor_sync(0xffffffffu, s, o);
    __shared__ float red[8];
    int lane = threadIdx.x & 31, w = threadIdx.x >> 5;
    if (lane == 0) red[w] = s;
    __syncthreads();
    __shared__ float invn;
    if (threadIdx.x == 0) {
        float t = 0.f;
        #pragma unroll
        for (int i = 0; i < 8; i++) t += red[i];
        invn = rsqrtf(t);
    }
    __syncthreads();
    float iv = invn;
    uint2 ow;
    *(bf162*)&ow.x = __floats2bfloat162_rn(a*iv, b*iv);
    *(bf162*)&ow.y = __floats2bfloat162_rn(c*iv, d*iv);
    *p = ow;
}

__global__ void zero_stats()
{
    int i = blockIdx.x * blockDim.x + threadIdx.x;
    if (i < 2*NS) { g_r11[i] = 0.f; g_r22[i] = 0.f; g_r12[i] = 0.f; g_c12[i] = 0.f; }
    if (i < 2) g_loss[i] = 0.f;
}

__global__ void loss_all()
{
    int v = blockIdx.z;
    int i = blockIdx.x * blockDim.x + threadIdx.x;
    float val = 0.f;
    if (i < NS) {
        int k = v*NS + i;
        float ld = logf(g_d12[k]);
        float l1 = logf(g_r11[k] + g_r12[k] - g_d11[k]) - ld;
        float l2 = logf(g_r22[k] + g_c12[k] - g_d22[k]) - ld;
        val = 0.5f * (l1 + l2) * (1.0f / NS);
    }
    #pragma unroll
    for (int o = 16; o; o >>= 1) val += __shfl_down_sync(0xffffffffu, val, o);
    if ((threadIdx.x & 31) == 0) atomicAdd(&g_loss[v], val);
}

__global__ void finalize_k(const float* __restrict__ w_r1, float* __restrict__ out)
{
    float w = fminf(fmaxf(w_r1[0], 0.f), 1.f);
    out[0] = w * g_loss[0] + (1.f - w) * g_loss[1];
}

// ----------------------------------------------------------------------------
extern "C" void kernel_launch(void* const* d_in, const int* in_sizes, int n_in,
                              void* d_out, int out_size)
{
    const float* ta   = (const float*)d_in[0];
    const float* tb   = (const float*)d_in[1];
    const float* W1   = (const float*)d_in[2];
    const float* b1   = (const float*)d_in[3];
    const float* W2   = (const float*)d_in[4];
    const float* b2   = (const float*)d_in[5];
    const float* W3   = (const float*)d_in[6];
    const float* b3   = (const float*)d_in[7];
    const float* W4   = (const float*)d_in[8];
    const float* b4   = (const float*)d_in[9];
    const float* w_r1 = (const float*)d_in[10];
    float* out = (float*)d_out;

    cudaFuncSetAttribute(proj1_all, cudaFuncAttributeMaxDynamicSharedMemorySize, SMEM_TOT);
    cudaFuncSetAttribute(proj2_all, cudaFuncAttributeMaxDynamicSharedMemorySize, SMEM_TOT);
    cudaFuncSetAttribute(sim_all,   cudaFuncAttributeMaxDynamicSharedMemorySize, SMEM_TOT);

    conv_all <<<dim3(2048, 1, 6), 256>>>(ta, tb, W1, W2, W3, W4);
    trans_all<<<dim3(NS, 1, 2), 256>>>(ta, tb);
    zero_stats<<<(2*NS + 255)/256, 256>>>();
    proj1_all<<<dim3(8, 64, 4), 256, SMEM_TOT>>>(b1, b3);
    proj2_all<<<dim3(8, 64, 4), 256, SMEM_TOT>>>(b2, b4);
    norm_all <<<dim3(NS, 1, 4), 256>>>();
    sim_all  <<<dim3(64, 64, 6), 256, SMEM_TOT>>>();
    loss_all <<<dim3(32, 1, 2), 256>>>();
    finalize_k<<<1, 1>>>(w_r1, out);
}

// round 17
// speedup vs baseline: 1.0576x; 1.0078x over previous
#include <cuda_runtime.h>
#include <cuda_bf16.h>
#include <math.h>
#include <stdint.h>

// TContrastive: bf16 mma.sync 128x128 tiles @ 2 CTAs/SM, cp.async 3-stage
// pipeline, K-chunk 64 (128B SW128 rows), 96KB dynamic smem, prefetch copies
// interleaved into the MMA stream, z-fused launches.

#define NS 8192
#define DD 1024
#define STAGE_B 32768             // A 16KB + B 16KB per stage; 3 stages = 96KB
#define SMEM_TOT (3 * STAGE_B)

typedef __nv_bfloat16 bf16;
typedef __nv_bfloat162 bf162;

__device__ bf16 b_A1[NS*DD],  b_A2[NS*DD];
__device__ bf16 b_A1c[NS*DD], b_A2c[NS*DD];
__device__ bf16 b_U1[NS*DD],  b_U2[NS*DD],  b_U1c[NS*DD], b_U2c[NS*DD];
__device__ bf16 b_H1[NS*DD],  b_H2[NS*DD],  b_H1c[NS*DD], b_H2c[NS*DD];
__device__ bf16 b_W1[DD*DD], b_W2[DD*DD], b_W3[DD*DD], b_W4[DD*DD];
__device__ float g_r11[2*NS], g_r22[2*NS], g_r12[2*NS], g_c12[2*NS];
__device__ float g_d11[2*NS], g_d22[2*NS], g_d12[2*NS];
__device__ float g_loss[2];

// ---------------- primitives -------------------------------------------------
__device__ __forceinline__ void ldm_x4(uint32_t& r0, uint32_t& r1, uint32_t& r2,
                                       uint32_t& r3, uint32_t a)
{
    asm volatile("ldmatrix.sync.aligned.m8n8.x4.shared.b16 {%0,%1,%2,%3}, [%4];"
                 : "=r"(r0), "=r"(r1), "=r"(r2), "=r"(r3) : "r"(a));
}
__device__ __forceinline__ void mma16816(float* c, const uint32_t* a, const uint32_t* b)
{
    asm volatile("mma.sync.aligned.m16n8k16.row.col.f32.bf16.bf16.f32 "
                 "{%0,%1,%2,%3}, {%4,%5,%6,%7}, {%8,%9}, {%0,%1,%2,%3};"
                 : "+f"(c[0]), "+f"(c[1]), "+f"(c[2]), "+f"(c[3])
                 : "r"(a[0]), "r"(a[1]), "r"(a[2]), "r"(a[3]), "r"(b[0]), "r"(b[1]));
}
__device__ __forceinline__ void cpa16(uint32_t dst, const void* src)
{ asm volatile("cp.async.cg.shared.global [%0], [%1], 16;" :: "r"(dst), "l"(src)); }
#define CP_COMMIT() asm volatile("cp.async.commit_group;" ::: "memory")
#define CP_WAIT1()  asm volatile("cp.async.wait_group 1;" ::: "memory")
#define CP_WAIT0()  asm volatile("cp.async.wait_group 0;" ::: "memory")

// SW128 swizzle for 128B rows: byte = row*128 + ((q ^ (row&7)) << 4), q = 16B col
__device__ __forceinline__ uint32_t swz128(int row, int q)
{ return (uint32_t)(row * 128 + ((q ^ (row & 7)) << 4)); }

// ---------------- mainloop: 128x128 fp32 tile of A·B^T, K=1024 --------------
// Warp grid 2x4; warp tile 64x32; acc[ti][tj][4]. K-chunk 64 (128B rows),
// 16 chunks, 3 stages (literal offsets), wait_group 1. Prefetch copies for
// chunk c+2 are interleaved 2-per-ks-group into chunk c's compute.
__device__ __forceinline__ void mma_mainloop(const bf16* __restrict__ A,
    const bf16* __restrict__ B, int m0, int n0, char* sm, float acc[4][4][4])
{
    const int tid = threadIdx.x, lane = tid & 31, wid = tid >> 5;
    const int wm = wid >> 2, wn = wid & 3;
    const int r = lane & 7, tsel = lane >> 3;
    const int a_row = ((tsel & 1) << 3) + r, a_col = (tsel >> 1) << 3;
    const int b_row = ((tsel >> 1) << 3) + r, b_col = (tsel & 1) << 3;

    const uint32_t smb = (uint32_t)__cvta_generic_to_shared(sm);
    const int cr = tid >> 3, cq = tid & 7;
    const char* spA = (const char*)(A + (size_t)(m0 + cr) * DD) + cq * 16;
    const char* spB = (const char*)(B + (size_t)(n0 + cr) * DD) + cq * 16;
    const uint32_t dA = smb + swz128(cr, cq);
    const uint32_t dB = dA + 16384u;

    #pragma unroll
    for (int i = 0; i < 4; i++)
        #pragma unroll
        for (int j = 0; j < 4; j++)
            #pragma unroll
            for (int p = 0; p < 4; p++) acc[i][j][p] = 0.f;

    // full chunk copy (prologue only)
    #define DO_COPY(soff)                                                        \
        do {                                                                     \
            cpa16(dA + (soff),          spA);                                    \
            cpa16(dA + (soff) + 4096u,  spA + 65536);                            \
            cpa16(dA + (soff) + 8192u,  spA + 131072);                           \
            cpa16(dA + (soff) + 12288u, spA + 196608);                           \
            cpa16(dB + (soff),          spB);                                    \
            cpa16(dB + (soff) + 4096u,  spB + 65536);                            \
            cpa16(dB + (soff) + 8192u,  spB + 131072);                           \
            cpa16(dB + (soff) + 12288u, spB + 196608);                           \
            CP_COMMIT();                                                         \
            spA += 128; spB += 128;                                              \
        } while (0)

    DO_COPY(0u);
    DO_COPY((uint32_t)STAGE_B);

    // one ks-group of ldmatrix + MMAs
    auto ksgroup = [&](uint32_t sA, uint32_t sB, int ks) {
        uint32_t a[4][4], b[4][2];
        int qa = (ks + a_col) >> 3, qb = (ks + b_col) >> 3;
        #pragma unroll
        for (int ti = 0; ti < 4; ti++) {
            int rr = wm*64 + ti*16 + a_row;
            ldm_x4(a[ti][0], a[ti][1], a[ti][2], a[ti][3], sA + swz128(rr, qa));
        }
        #pragma unroll
        for (int pp = 0; pp < 2; pp++) {
            int rr = wn*32 + pp*16 + b_row;
            ldm_x4(b[2*pp][0], b[2*pp][1], b[2*pp+1][0], b[2*pp+1][1],
                   sB + swz128(rr, qb));
        }
        #pragma unroll
        for (int ti = 0; ti < 4; ti++)
            #pragma unroll
            for (int tj = 0; tj < 4; tj++)
                mma16816(acc[ti][tj], a[ti], b[tj]);
    };

    // compute chunk at stage cs while issuing chunk c+2's copies into poff,
    // 2 copies per ks-group; commit at end of chunk.
    auto compute_pf = [&](uint32_t cs, uint32_t poff) {
        const uint32_t sA = smb + cs;
        const uint32_t sB = sA + 16384u;
        cpa16(dA + poff,          spA);
        cpa16(dA + poff + 4096u,  spA + 65536);
        ksgroup(sA, sB, 0);
        cpa16(dA + poff + 8192u,  spA + 131072);
        cpa16(dA + poff + 12288u, spA + 196608);
        ksgroup(sA, sB, 16);
        cpa16(dB + poff,          spB);
        cpa16(dB + poff + 4096u,  spB + 65536);
        ksgroup(sA, sB, 32);
        cpa16(dB + poff + 8192u,  spB + 131072);
        cpa16(dB + poff + 12288u, spB + 196608);
        ksgroup(sA, sB, 48);
        CP_COMMIT();
        spA += 128; spB += 128;
    };
    auto compute_only = [&](uint32_t cs) {
        const uint32_t sA = smb + cs;
        const uint32_t sB = sA + 16384u;
        ksgroup(sA, sB, 0);  ksgroup(sA, sB, 16);
        ksgroup(sA, sB, 32); ksgroup(sA, sB, 48);
    };

    #define PIPE_STEP(cs, poff)                                                  \
        do { CP_WAIT1(); __syncthreads(); compute_pf(cs, poff); } while (0)

    #pragma unroll 1
    for (int cb = 0; cb < 12; cb += 3) {          // c = 0..11, prefetch 2..13
        PIPE_STEP(0u,                  2u*STAGE_B);
        PIPE_STEP((uint32_t)STAGE_B,   0u);
        PIPE_STEP(2u*STAGE_B,          (uint32_t)STAGE_B);
    }
    PIPE_STEP(0u,                2u*STAGE_B);     // c=12, prefetch 14
    PIPE_STEP((uint32_t)STAGE_B, 0u);             // c=13, prefetch 15
    #undef PIPE_STEP
    #undef DO_COPY
    CP_WAIT1(); __syncthreads(); compute_only(2u*STAGE_B);   // c=14
    CP_WAIT0(); __syncthreads(); compute_only(0u);           // c=15
}

// ---------------- projection GEMM body --------------------------------------
template<int MODE>
__device__ __forceinline__ void gemm_body(const bf16* __restrict__ A,
    const bf16* __restrict__ W, const float* __restrict__ bias, bf16* __restrict__ C)
{
    extern __shared__ __align__(16) char sm[];
    const int m0 = blockIdx.y * 128, n0 = blockIdx.x * 128;
    const int lane = threadIdx.x & 31, wid = threadIdx.x >> 5;
    const int wm = wid >> 2, wn = wid & 3;
    const int grp = lane >> 2, qid = lane & 3;

    float acc[4][4][4];
    mma_mainloop(A, W, m0, n0, sm, acc);

    #pragma unroll
    for (int tj = 0; tj < 4; tj++) {
        int gc = n0 + wn*32 + tj*8 + qid*2;
        float bv0 = bias[gc], bv1 = bias[gc+1];
        #pragma unroll
        for (int ti = 0; ti < 4; ti++)
            #pragma unroll
            for (int h = 0; h < 2; h++) {
                int gr = m0 + wm*64 + ti*16 + h*8 + grp;
                float v0 = acc[ti][tj][h*2+0] + bv0;
                float v1 = acc[ti][tj][h*2+1] + bv1;
                if (MODE == 1) {
                    v0 = v0 > 0.f ? v0 : expm1f(v0);
                    v1 = v1 > 0.f ? v1 : expm1f(v1);
                }
                *(bf162*)(C + (size_t)gr * DD + gc) = __floats2bfloat162_rn(v0, v1);
            }
    }
}

__global__ __launch_bounds__(256, 2) void proj1_all(const float* b1, const float* b3)
{
    int z = blockIdx.z;
    const bf16 *A, *W; bf16* C;
    if (z == 0)      { A = b_A1;  W = b_W1; C = b_U1;  }
    else if (z == 1) { A = b_A2;  W = b_W1; C = b_U2;  }
    else if (z == 2) { A = b_A1c; W = b_W3; C = b_U1c; }
    else             { A = b_A2c; W = b_W3; C = b_U2c; }
    gemm_body<1>(A, W, (z < 2) ? b1 : b3, C);
}
__global__ __launch_bounds__(256, 2) void proj2_all(const float* b2, const float* b4)
{
    int z = blockIdx.z;
    const bf16 *A, *W; bf16* C;
    if (z == 0)      { A = b_U1;  W = b_W2; C = b_H1;  }
    else if (z == 1) { A = b_U2;  W = b_W2; C = b_H2;  }
    else if (z == 2) { A = b_U1c; W = b_W4; C = b_H1c; }
    else             { A = b_U2c; W = b_W4; C = b_H2c; }
    gemm_body<0>(A, W, (z < 2) ? b2 : b4, C);
}

// ---------------- fused similarity: all 6 matrices in one launch -------------
__global__ __launch_bounds__(256, 2) void sim_all()
{
    const int z = blockIdx.z;
    const int v = z / 3, m = z % 3;
    const bool SYM = (m != 2);
    const int bi = blockIdx.y;
    const int bj = SYM ? (bi + blockIdx.x) : blockIdx.x;
    if (SYM && bj >= 64) return;

    const bf16 *A, *B;
    float *rs, *cs, *dg;
    if (v == 0) {
        A = (m == 1) ? b_H2 : b_H1;
        B = (m == 0) ? b_H1 : b_H2;
        rs = (m == 0) ? g_r11 : (m == 1) ? g_r22 : g_r12;
        dg = (m == 0) ? g_d11 : (m == 1) ? g_d22 : g_d12;
    } else {
        A = (m == 1) ? b_H2c : b_H1c;
        B = (m == 0) ? b_H1c : b_H2c;
        rs = ((m == 0) ? g_r11 : (m == 1) ? g_r22 : g_r12) + NS;
        dg = ((m == 0) ? g_d11 : (m == 1) ? g_d22 : g_d12) + NS;
    }
    cs = SYM ? rs : (g_c12 + v*NS);

    extern __shared__ __align__(16) char sm[];
    const int m0 = bi * 128, n0 = bj * 128;
    const int lane = threadIdx.x & 31, wid = threadIdx.x >> 5;
    const int wm = wid >> 2, wn = wid & 3;
    const int grp = lane >> 2, qid = lane & 3;
    const bool diag = (bi == bj);
    const bool doCols = (!SYM) || (bj > bi);

    float acc[4][4][4];
    mma_mainloop(A, B, m0, n0, sm, acc);

    #pragma unroll
    for (int ti = 0; ti < 4; ti++)
        #pragma unroll
        for (int h = 0; h < 2; h++) {
            int gr = m0 + wm*64 + ti*16 + h*8 + grp;
            float rsum = 0.f;
            #pragma unroll
            for (int tj = 0; tj < 4; tj++) {
                int gc = n0 + wn*32 + tj*8 + qid*2;
                float e0 = __expf(2.f * acc[ti][tj][h*2+0]);
                float e1 = __expf(2.f * acc[ti][tj][h*2+1]);
                acc[ti][tj][h*2+0] = e0;
                acc[ti][tj][h*2+1] = e1;
                rsum += e0 + e1;
                if (diag) {
                    if (gr == gc)     dg[gr] = e0;
                    if (gr == gc + 1) dg[gr] = e1;
                }
            }
            rsum += __shfl_down_sync(0xffffffffu, rsum, 2, 4);
            rsum += __shfl_down_sync(0xffffffffu, rsum, 1, 4);
            if (qid == 0) atomicAdd(&rs[gr], rsum);
        }

    if (doCols) {
        #pragma unroll
        for (int tj = 0; tj < 4; tj++) {
            float c0 = 0.f, c1 = 0.f;
            #pragma unroll
            for (int ti = 0; ti < 4; ti++) {
                c0 += acc[ti][tj][0] + acc[ti][tj][2];
                c1 += acc[ti][tj][1] + acc[ti][tj][3];
            }
            #pragma unroll
            for (int o = 4; o <= 16; o <<= 1) {
                c0 += __shfl_xor_sync(0xffffffffu, c0, o);
                c1 += __shfl_xor_sync(0xffffffffu, c1, o);
            }
            if (grp == 0) {
                int gc = n0 + wn*32 + tj*8 + qid*2;
                atomicAdd(&cs[gc],   c0);
                atomicAdd(&cs[gc+1], c1);
            }
        }
    }
}

// ---------------- aux kernels (z-fused) --------------------------------------
__global__ void conv_all(const float* ta, const float* tb,
                         const float* W1, const float* W2,
                         const float* W3, const float* W4)
{
    int z = blockIdx.z;
    int nblk = (z < 2) ? 2048 : 256;
    if (blockIdx.x >= (unsigned)nblk) return;
    const float* s; bf16* d;
    if (z == 0)      { s = ta; d = b_A1; }
    else if (z == 1) { s = tb; d = b_A2; }
    else if (z == 2) { s = W1; d = b_W1; }
    else if (z == 3) { s = W2; d = b_W2; }
    else if (z == 4) { s = W3; d = b_W3; }
    else             { s = W4; d = b_W4; }
    int i = blockIdx.x * blockDim.x + threadIdx.x;
    int st = nblk * 256;
    float4 v0 = ((const float4*)s)[i];
    float4 v1 = ((const float4*)s)[i + st];
    float4 v2 = ((const float4*)s)[i + 2*st];
    float4 v3 = ((const float4*)s)[i + 3*st];
    ((bf162*)d)[(i)*2+0]      = __floats2bfloat162_rn(v0.x, v0.y);
    ((bf162*)d)[(i)*2+1]      = __floats2bfloat162_rn(v0.z, v0.w);
    ((bf162*)d)[(i+st)*2+0]   = __floats2bfloat162_rn(v1.x, v1.y);
    ((bf162*)d)[(i+st)*2+1]   = __floats2bfloat162_rn(v1.z, v1.w);
    ((bf162*)d)[(i+2*st)*2+0] = __floats2bfloat162_rn(v2.x, v2.y);
    ((bf162*)d)[(i+2*st)*2+1] = __floats2bfloat162_rn(v2.z, v2.w);
    ((bf162*)d)[(i+3*st)*2+0] = __floats2bfloat162_rn(v3.x, v3.y);
    ((bf162*)d)[(i+3*st)*2+1] = __floats2bfloat162_rn(v3.z, v3.w);
}

__global__ __launch_bounds__(256) void trans_all(const float* ta, const float* tb)
{
    const float* in = blockIdx.z ? tb : ta;
    bf16* out = blockIdx.z ? b_A2c : b_A1c;
    __shared__ float t[32][33];
    const float* s = in  + (size_t)blockIdx.x * 1024;
    bf16*        d = out + (size_t)blockIdx.x * 1024;
    for (int i = threadIdx.x; i < 1024; i += 256) t[i >> 5][i & 31] = s[i];
    __syncthreads();
    for (int i = threadIdx.x; i < 1024; i += 256)
        d[i] = __float2bfloat16(t[i & 31][i >> 5]);
}

__global__ __launch_bounds__(256) void norm_all()
{
    bf16* H = (blockIdx.z == 0) ? b_H1 : (blockIdx.z == 1) ? b_H2
            : (blockIdx.z == 2) ? b_H1c : b_H2c;
    int row = blockIdx.x;
    uint2* p = (uint2*)(H + (size_t)row * DD) + threadIdx.x;
    uint2 raw = *p;
    bf162 v0 = *(bf162*)&raw.x;
    bf162 v1 = *(bf162*)&raw.y;
    float a = __bfloat162float(v0.x), b = __bfloat162float(v0.y);
    float c = __bfloat162float(v1.x), d = __bfloat162float(v1.y);
    float s = a*a + b*b + c*c + d*d;
    #pragma unroll
    for (int o = 16; o; o >>= 1) s += __shfl_xor_sync(0xffffffffu, s, o);
    __shared__ float red[8];
    int lane = threadIdx.x & 31, w = threadIdx.x >> 5;
    if (lane == 0) red[w] = s;
    __syncthreads();
    __shared__ float invn;
    if (threadIdx.x == 0) {
        float t = 0.f;
        #pragma unroll
        for (int i = 0; i < 8; i++) t += red[i];
        invn = rsqrtf(t);
    }
    __syncthreads();
    float iv = invn;
    uint2 ow;
    *(bf162*)&ow.x = __floats2bfloat162_rn(a*iv, b*iv);
    *(bf162*)&ow.y = __floats2bfloat162_rn(c*iv, d*iv);
    *p = ow;
}

__global__ void zero_stats()
{
    int i = blockIdx.x * blockDim.x + threadIdx.x;
    if (i < 2*NS) { g_r11[i] = 0.f; g_r22[i] = 0.f; g_r12[i] = 0.f; g_c12[i] = 0.f; }
    if (i < 2) g_loss[i] = 0.f;
}

__global__ void loss_all()
{
    int v = blockIdx.z;
    int i = blockIdx.x * blockDim.x + threadIdx.x;
    float val = 0.f;
    if (i < NS) {
        int k = v*NS + i;
        float ld = logf(g_d12[k]);
        float l1 = logf(g_r11[k] + g_r12[k] - g_d11[k]) - ld;
        float l2 = logf(g_r22[k] + g_c12[k] - g_d22[k]) - ld;
        val = 0.5f * (l1 + l2) * (1.0f / NS);
    }
    #pragma unroll
    for (int o = 16; o; o >>= 1) val += __shfl_down_sync(0xffffffffu, val, o);
    if ((threadIdx.x & 31) == 0) atomicAdd(&g_loss[v], val);
}

__global__ void finalize_k(const float* __restrict__ w_r1, float* __restrict__ out)
{
    float w = fminf(fmaxf(w_r1[0], 0.f), 1.f);
    out[0] = w * g_loss[0] + (1.f - w) * g_loss[1];
}

// ----------------------------------------------------------------------------
extern "C" void kernel_launch(void* const* d_in, const int* in_sizes, int n_in,
                              void* d_out, int out_size)
{
    const float* ta   = (const float*)d_in[0];
    const float* tb   = (const float*)d_in[1];
    const float* W1   = (const float*)d_in[2];
    const float* b1   = (const float*)d_in[3];
    const float* W2   = (const float*)d_in[4];
    const float* b2   = (const float*)d_in[5];
    const float* W3   = (const float*)d_in[6];
    const float* b3   = (const float*)d_in[7];
    const float* W4   = (const float*)d_in[8];
    const float* b4   = (const float*)d_in[9];
    const float* w_r1 = (const float*)d_in[10];
    float* out = (float*)d_out;

    cudaFuncSetAttribute(proj1_all, cudaFuncAttributeMaxDynamicSharedMemorySize, SMEM_TOT);
    cudaFuncSetAttribute(proj2_all, cudaFuncAttributeMaxDynamicSharedMemorySize, SMEM_TOT);
    cudaFuncSetAttribute(sim_all,   cudaFuncAttributeMaxDynamicSharedMemorySize, SMEM_TOT);

    conv_all <<<dim3(2048, 1, 6), 256>>>(ta, tb, W1, W2, W3, W4);
    trans_all<<<dim3(NS, 1, 2), 256>>>(ta, tb);
    zero_stats<<<(2*NS + 255)/256, 256>>>();
    proj1_all<<<dim3(8, 64, 4), 256, SMEM_TOT>>>(b1, b3);
    proj2_all<<<dim3(8, 64, 4), 256, SMEM_TOT>>>(b2, b4);
    norm_all <<<dim3(NS, 1, 4), 256>>>();
    sim_all  <<<dim3(64, 64, 6), 256, SMEM_TOT>>>();
    loss_all <<<dim3(32, 1, 2), 256>>>();
    finalize_k<<<1, 1>>>(w_r1, out);
}